// round 7
// baseline (speedup 1.0000x reference)
#include <cuda_runtime.h>
#include <cuda_bf16.h>
#include <cstdint>

// Problem constants (fixed by setup_inputs)
#define BATCH 4
#define MDIM 4096
#define NDIM 32
#define CDIM 256
#define DDIM 128
#define ROWS (BATCH * MDIM)        // 16384
#define LN_EPS 1e-5f
#define SCALE 0.08838834764831845f // 1/sqrt(128)

// mega-kernel tiling: 32-row tiles, 4 gemm blocks (64 cols each) + 32 attn blocks per tile
#define NTILE 512                  // 16384 / 32
#define L_LEAD 24                  // gemm runs L_LEAD tiles ahead of attn
#define PRO (4 * L_LEAD)           // prologue gemm blocks (tiles 0..L_LEAD-1)
#define MIDB ((NTILE - L_LEAD) * 36)
#define TOTB (PRO + MIDB + L_LEAD * 32)   // = 18432

// ---------------- scratch (device globals, no allocation) ----------------
__device__ __align__(16) float g_Mraw[CDIM * CDIM]; // Wq @ Wk^T
__device__ __align__(16) float g_M2[CDIM * CDIM];   // Mraw[c][c'] * k_gamma[c']
__device__ __align__(16) float g_bv[CDIM];          // Wk[c',:]·bq
__device__ __align__(16) float g_bv2[CDIM];         // k_gamma * bv
__device__ __align__(16) float g_rowvec[CDIM];      // mb[c] + u[c]
__device__ float g_const[1];                        // cb + bb
__device__ float2 g_stat[ROWS];                     // {mu, rs} per row of x
__device__ __align__(16) float g_w[ROWS * CDIM];    // per-row weight vectors
__device__ float g_Bc[ROWS];                        // per-row scalar bias
__device__ int g_flag[NTILE];                       // per-tile ready counters

// ---------------- helpers ----------------
__device__ __forceinline__ float blockSum256(float v, float* s8) {
    #pragma unroll
    for (int o = 16; o; o >>= 1) v += __shfl_xor_sync(0xffffffffu, v, o);
    __syncthreads();
    if ((threadIdx.x & 31) == 0) s8[threadIdx.x >> 5] = v;
    __syncthreads();
    float tot = 0.f;
    #pragma unroll
    for (int i = 0; i < 8; i++) tot += s8[i];
    return tot;
}

#define FMA2(d, a, b) \
    asm("fma.rn.f32x2 %0, %1, %2, %0;" : "+l"(d) : "l"(a), "l"(b))
#define PACK2(out, lo, hi) \
    asm("mov.b64 %0, {%1, %2};" : "=l"(out) : "r"(__float_as_uint(lo)), "r"(__float_as_uint(hi)))

__device__ __forceinline__ float2 unpack2(unsigned long long v) {
    unsigned int lo, hi;
    asm("mov.b64 {%0, %1}, %2;" : "=r"(lo), "=r"(hi) : "l"(v));
    return make_float2(__uint_as_float(lo), __uint_as_float(hi));
}

// ---------------- K1a: Mraw = Wq(256x128) @ Wk^T(128x256), tiled ----------------
__global__ void prepA_kernel(const float* __restrict__ Wq, const float* __restrict__ Wk) {
    __shared__ float As[32][68];
    __shared__ float Bs[32][68];
    const int bm = blockIdx.y * 64;
    const int bn = blockIdx.x * 64;
    const int tid = threadIdx.x;
    const int tx = tid & 15, ty = tid >> 4;
    const int r = tid >> 2, dq = tid & 3;

    float acc[4][4];
    #pragma unroll
    for (int i = 0; i < 4; i++)
        #pragma unroll
        for (int j = 0; j < 4; j++) acc[i][j] = 0.f;

    for (int k0 = 0; k0 < DDIM; k0 += 32) {
        float4 a0 = *(const float4*)(Wq + (size_t)(bm + r) * DDIM + k0 + dq * 8);
        float4 a1 = *(const float4*)(Wq + (size_t)(bm + r) * DDIM + k0 + dq * 8 + 4);
        float4 b0 = *(const float4*)(Wk + (size_t)(bn + r) * DDIM + k0 + dq * 8);
        float4 b1 = *(const float4*)(Wk + (size_t)(bn + r) * DDIM + k0 + dq * 8 + 4);
        As[dq * 8 + 0][r] = a0.x; As[dq * 8 + 1][r] = a0.y;
        As[dq * 8 + 2][r] = a0.z; As[dq * 8 + 3][r] = a0.w;
        As[dq * 8 + 4][r] = a1.x; As[dq * 8 + 5][r] = a1.y;
        As[dq * 8 + 6][r] = a1.z; As[dq * 8 + 7][r] = a1.w;
        Bs[dq * 8 + 0][r] = b0.x; Bs[dq * 8 + 1][r] = b0.y;
        Bs[dq * 8 + 2][r] = b0.z; Bs[dq * 8 + 3][r] = b0.w;
        Bs[dq * 8 + 4][r] = b1.x; Bs[dq * 8 + 5][r] = b1.y;
        Bs[dq * 8 + 6][r] = b1.z; Bs[dq * 8 + 7][r] = b1.w;
        __syncthreads();
        #pragma unroll
        for (int k = 0; k < 32; k++) {
            float4 a = *(const float4*)&As[k][ty * 4];
            float4 b = *(const float4*)&Bs[k][tx * 4];
            float ai[4] = {a.x, a.y, a.z, a.w};
            float bj[4] = {b.x, b.y, b.z, b.w};
            #pragma unroll
            for (int i = 0; i < 4; i++)
                #pragma unroll
                for (int j = 0; j < 4; j++) acc[i][j] += ai[i] * bj[j];
        }
        __syncthreads();
    }
    #pragma unroll
    for (int i = 0; i < 4; i++)
        *(float4*)(g_Mraw + (size_t)(bm + ty * 4 + i) * CDIM + bn + tx * 4) =
            make_float4(acc[i][0], acc[i][1], acc[i][2], acc[i][3]);
}

// ---------------- K1b: per-c derived vectors ----------------
__global__ void prepB_kernel(const float* __restrict__ Wq, const float* __restrict__ Wk,
                             const float* __restrict__ bq, const float* __restrict__ bk,
                             const float* __restrict__ kg, const float* __restrict__ kb) {
    const int c = blockIdx.x;
    const int t = threadIdx.x;
    __shared__ float s8[8];
    float mraw = g_Mraw[(size_t)c * CDIM + t];
    g_M2[(size_t)c * CDIM + t] = mraw * kg[t];
    float mb = blockSum256(mraw * kb[t], s8);
    float u  = blockSum256(t < DDIM ? Wq[(size_t)c * DDIM + t] * bk[t] : 0.f, s8);
    float bv = blockSum256(t < DDIM ? Wk[(size_t)c * DDIM + t] * bq[t] : 0.f, s8);
    if (t == 0) {
        g_rowvec[c] = mb + u;
        g_bv[c] = bv;
        g_bv2[c] = bv * kg[c];
    }
}

// ---------------- K2: stats (warp/row) + flag reset + g_const ----------------
__global__ void __launch_bounds__(256)
stats_kernel(const float* __restrict__ x, const float* __restrict__ Wk,
             const float* __restrict__ kb, const float* __restrict__ bk,
             const float* __restrict__ bq) {
    const int bid = blockIdx.x;
    const int tid = threadIdx.x;
    if (bid < ROWS / 8) {
        if (bid < NTILE && tid == 0) g_flag[bid] = 0;   // reset per-tile flags
        const int w = tid >> 5, l = tid & 31;
        const int row = bid * 8 + w;
        const float* xr = x + (size_t)row * CDIM + l * 8;
        float4 xa = *(const float4*)(xr);
        float4 xb = *(const float4*)(xr + 4);
        float s1 = xa.x + xa.y + xa.z + xa.w + xb.x + xb.y + xb.z + xb.w;
        float s2 = xa.x*xa.x + xa.y*xa.y + xa.z*xa.z + xa.w*xa.w
                 + xb.x*xb.x + xb.y*xb.y + xb.z*xb.z + xb.w*xb.w;
        #pragma unroll
        for (int o = 16; o; o >>= 1) {
            s1 += __shfl_xor_sync(0xffffffffu, s1, o);
            s2 += __shfl_xor_sync(0xffffffffu, s2, o);
        }
        if (l == 0) {
            float mu = s1 * (1.f / CDIM);
            float var = s2 * (1.f / CDIM) - mu * mu;
            g_stat[row] = make_float2(mu, rsqrtf(var + LN_EPS));
        }
    } else {
        // g_const = bq . (Wk^T kb + bk)
        __shared__ float s8[8];
        float acc = 0.f;
        if (tid < DDIM) {
            for (int c = 0; c < CDIM; c++) acc += Wk[(size_t)c * DDIM + tid] * kb[c];
            acc = (acc + bk[tid]) * bq[tid];
        }
        float tot = blockSum256(acc, s8);
        if (tid == 0) g_const[0] = tot;
    }
}

// ---------------- K3: MEGA kernel — gemm producers + attn consumers ----------------
__global__ void __launch_bounds__(256, 4)
mega_kernel(const float* __restrict__ x, const float* __restrict__ y,
            const float* __restrict__ z, const float* __restrict__ qg,
            const float* __restrict__ qb, float* __restrict__ out) {
    __shared__ __align__(16) float As[16][34];   // gemm A [k][m]
    __shared__ __align__(16) float Bs[16][68];   // gemm B [k][n]
    __shared__ __align__(16) float sw[CDIM];     // attn w row
    __shared__ float s8[8];
    __shared__ float sdot[NDIM];

    const int bid = blockIdx.x;
    const int tid = threadIdx.x;

    // ---- role decode ----
    int tile = -1, bn = 0, row = -1;
    if (bid < PRO) {
        tile = bid >> 2; bn = bid & 3;
    } else if (bid < PRO + MIDB) {
        const int b2 = bid - PRO;
        const int j = b2 / 36, lo = b2 - j * 36;
        if (lo < 4) { tile = j + L_LEAD; bn = lo; }
        else        { row = j * 32 + lo - 4; }
    } else {
        const int b3 = bid - PRO - MIDB;
        row = (NTILE - L_LEAD) * 32 + b3;   // tail: attn rows for last L_LEAD tiles
    }

    if (tile >= 0) {
        // ================= GEMM producer: 32(M) x 64(N) tile =================
        const int mbase = tile * 32, nbase = bn * 64;
        const int ar = tid >> 3, ak = (tid & 7) * 2;    // A staging: row, k-pair
        const int bkr = tid >> 4, bc = (tid & 15) * 4;  // B staging
        const int tx = tid & 15, ty = tid >> 4;         // compute: 4 cols, 2 rows

        const float2 st = g_stat[mbase + ar];
        const float* xq = x + (size_t)(mbase + ar) * CDIM + ak;
        const float* bpg = g_M2 + (size_t)bkr * CDIM + nbase + bc;

        unsigned long long a00 = 0ull, a01 = 0ull, a10 = 0ull, a11 = 0ull;
        float bcacc = 0.f;

        float2 xa  = *(const float2*)(xq);
        float2 gq2 = *(const float2*)(qg + ak);
        float2 gb2 = *(const float2*)(qb + ak);
        float2 rv2 = *(const float2*)(g_rowvec + ak);
        float4 bv4 = *(const float4*)(bpg);

        for (int k0 = 0; k0 < CDIM; k0 += 16) {
            float u0 = (xa.x - st.x) * st.y;
            float u1 = (xa.y - st.x) * st.y;
            float l0 = fmaf(u0, gq2.x, gb2.x);
            float l1 = fmaf(u1, gq2.y, gb2.y);
            As[ak][ar] = l0;
            As[ak + 1][ar] = l1;
            bcacc += l0 * rv2.x + l1 * rv2.y;
            *(float4*)&Bs[bkr][bc] = bv4;
            __syncthreads();

            if (k0 + 16 < CDIM) {
                xa  = *(const float2*)(xq + k0 + 16);
                gq2 = *(const float2*)(qg + k0 + 16 + ak);
                gb2 = *(const float2*)(qb + k0 + 16 + ak);
                rv2 = *(const float2*)(g_rowvec + k0 + 16 + ak);
                bv4 = *(const float4*)(bpg + (size_t)(k0 + 16) * CDIM);
            }

            #pragma unroll
            for (int k = 0; k < 16; k++) {
                float2 a = *(const float2*)&As[k][ty * 2];
                const unsigned long long* bp = (const unsigned long long*)&Bs[k][tx * 4];
                unsigned long long b01 = bp[0], b23 = bp[1];
                unsigned long long ad;
                PACK2(ad, a.x, a.x);
                FMA2(a00, ad, b01);
                FMA2(a01, ad, b23);
                PACK2(ad, a.y, a.y);
                FMA2(a10, ad, b01);
                FMA2(a11, ad, b23);
            }
            __syncthreads();
        }

        // Bc (bn==0 only): reduce over the 8 k-lanes sharing row ar
        bcacc += __shfl_xor_sync(0xffffffffu, bcacc, 1);
        bcacc += __shfl_xor_sync(0xffffffffu, bcacc, 2);
        bcacc += __shfl_xor_sync(0xffffffffu, bcacc, 4);
        if (bn == 0 && (tid & 7) == 0)
            g_Bc[mbase + ar] = bcacc + g_const[0];

        float4 bias = *(const float4*)(g_bv2 + nbase + tx * 4);
        {
            const int r0 = mbase + ty * 2;
            float2 p0 = unpack2(a00), p1 = unpack2(a01);
            float2 p2 = unpack2(a10), p3 = unpack2(a11);
            *(float4*)(g_w + (size_t)r0 * CDIM + nbase + tx * 4) =
                make_float4(p0.x + bias.x, p0.y + bias.y, p1.x + bias.z, p1.y + bias.w);
            *(float4*)(g_w + (size_t)(r0 + 1) * CDIM + nbase + tx * 4) =
                make_float4(p2.x + bias.x, p2.y + bias.y, p3.x + bias.z, p3.y + bias.w);
        }
        __threadfence();
        __syncthreads();
        if (tid == 0) atomicAdd(&g_flag[tile], 1);
    } else {
        // ================= ATTN consumer =================
        const int wtile = row >> 5;
        if (tid == 0) {
            while (atomicAdd(&g_flag[wtile], 0) != 4) __nanosleep(200);
            __threadfence();
        }
        __syncthreads();

        float wv = g_w[(size_t)row * CDIM + tid];
        sw[tid] = wv;
        float G = blockSum256(wv, s8);   // includes syncthreads -> sw visible

        const int n = tid >> 3, t8 = tid & 7;
        const float* yr = y + ((size_t)row * NDIM + n) * CDIM;
        float S1 = 0.f, S2 = 0.f, S3 = 0.f;
        #pragma unroll
        for (int j = 0; j < 8; j++) {
            const int col = j * 32 + t8 * 4;
            float4 yv = __ldcs((const float4*)(yr + col));
            float4 w4 = *(const float4*)(sw + col);
            S1 += yv.x + yv.y + yv.z + yv.w;
            S2 += yv.x * yv.x + yv.y * yv.y + yv.z * yv.z + yv.w * yv.w;
            S3 += yv.x * w4.x + yv.y * w4.y + yv.z * w4.z + yv.w * w4.w;
        }
        #pragma unroll
        for (int o = 4; o; o >>= 1) {
            S1 += __shfl_down_sync(0xffffffffu, S1, o);
            S2 += __shfl_down_sync(0xffffffffu, S2, o);
            S3 += __shfl_down_sync(0xffffffffu, S3, o);
        }
        if (t8 == 0) {
            float mu = S1 * (1.f / CDIM);
            float var = S2 * (1.f / CDIM) - mu * mu;
            float rs = rsqrtf(var + LN_EPS);
            sdot[n] = SCALE * (rs * (S3 - mu * G) + g_Bc[row]);
        }
        __syncthreads();
        if (tid < NDIM) {
            float v = sdot[tid];
            float m = v;
            #pragma unroll
            for (int o = 16; o; o >>= 1) m = fmaxf(m, __shfl_xor_sync(0xffffffffu, m, o));
            float e = expf(v - m);
            float zb = z[(size_t)row * NDIM + tid];
            float se = e, sez = e * zb;
            #pragma unroll
            for (int o = 16; o; o >>= 1) {
                se += __shfl_xor_sync(0xffffffffu, se, o);
                sez += __shfl_xor_sync(0xffffffffu, sez, o);
            }
            if (tid == 0) out[row] = sez / se;
        }
    }
}

// ---------------- launch ----------------
extern "C" void kernel_launch(void* const* d_in, const int* in_sizes, int n_in,
                              void* d_out, int out_size) {
    const float* x  = (const float*)d_in[0];
    const float* y  = (const float*)d_in[1];
    const float* z  = (const float*)d_in[2];
    const float* qg = (const float*)d_in[3];
    const float* qb = (const float*)d_in[4];
    const float* Wq = (const float*)d_in[5];
    const float* bq = (const float*)d_in[6];
    const float* kg = (const float*)d_in[7];
    const float* kb = (const float*)d_in[8];
    const float* Wk = (const float*)d_in[9];
    const float* bk = (const float*)d_in[10];
    float* out = (float*)d_out;

    stats_kernel<<<ROWS / 8 + 1, 256>>>(x, Wk, kb, bk, bq);
    prepA_kernel<<<dim3(4, 4), 256>>>(Wq, Wk);
    prepB_kernel<<<CDIM, 256>>>(Wq, Wk, bq, bk, kg, kb);
    mega_kernel<<<TOTB, 256>>>(x, y, z, qg, qb, out);
}

// round 9
// speedup vs baseline: 1.3008x; 1.3008x over previous
#include <cuda_runtime.h>
#include <cuda_bf16.h>
#include <mma.h>
#include <cstdint>

using namespace nvcuda;

// Problem constants (fixed by setup_inputs)
#define BATCH 4
#define MDIM 4096
#define NDIM 32
#define CDIM 256
#define DDIM 128
#define ROWS (BATCH * MDIM)        // 16384
#define LN_EPS 1e-5f
#define SCALE 0.08838834764831845f // 1/sqrt(128)

// ---------------- scratch (device globals, no allocation) ----------------
__device__ __align__(16) float g_Mraw[CDIM * CDIM]; // Wq @ Wk^T
__device__ __align__(16) float g_M2[CDIM * CDIM];   // Mraw[c][c'] * k_gamma[c']
__device__ __align__(16) float g_bv[CDIM];          // Wk[c',:]·bq
__device__ __align__(16) float g_bv2[CDIM];         // k_gamma * bv
__device__ __align__(16) float g_rowvec[CDIM];      // mb[c] + u[c]
__device__ float g_const[1];                        // bq·(Wk^T kb + bk)
__device__ float2 g_stat[ROWS];                     // {mu, rs} per row of x
__device__ __align__(16) float g_w[ROWS * CDIM];    // per-row weight vectors
__device__ float g_Bc[ROWS];                        // per-row scalar bias

// ---------------- helpers ----------------
__device__ __forceinline__ float blockSum256(float v, float* s8) {
    #pragma unroll
    for (int o = 16; o; o >>= 1) v += __shfl_xor_sync(0xffffffffu, v, o);
    __syncthreads();
    if ((threadIdx.x & 31) == 0) s8[threadIdx.x >> 5] = v;
    __syncthreads();
    float tot = 0.f;
    #pragma unroll
    for (int i = 0; i < 8; i++) tot += s8[i];
    return tot;
}

__device__ __forceinline__ float tf32_rna(float v) {
    uint32_t u;
    asm("cvt.rna.tf32.f32 %0, %1;" : "=r"(u) : "f"(v));
    return __uint_as_float(u);
}

// ---------------- K1a: Mraw = Wq(256x128) @ Wk^T(128x256), tiled ----------------
__global__ void prepA_kernel(const float* __restrict__ Wq, const float* __restrict__ Wk) {
    __shared__ float As[32][68];
    __shared__ float Bs[32][68];
    const int bm = blockIdx.y * 64;
    const int bn = blockIdx.x * 64;
    const int tid = threadIdx.x;
    const int tx = tid & 15, ty = tid >> 4;
    const int r = tid >> 2, dq = tid & 3;

    float acc[4][4];
    #pragma unroll
    for (int i = 0; i < 4; i++)
        #pragma unroll
        for (int j = 0; j < 4; j++) acc[i][j] = 0.f;

    for (int k0 = 0; k0 < DDIM; k0 += 32) {
        float4 a0 = *(const float4*)(Wq + (size_t)(bm + r) * DDIM + k0 + dq * 8);
        float4 a1 = *(const float4*)(Wq + (size_t)(bm + r) * DDIM + k0 + dq * 8 + 4);
        float4 b0 = *(const float4*)(Wk + (size_t)(bn + r) * DDIM + k0 + dq * 8);
        float4 b1 = *(const float4*)(Wk + (size_t)(bn + r) * DDIM + k0 + dq * 8 + 4);
        As[dq * 8 + 0][r] = a0.x; As[dq * 8 + 1][r] = a0.y;
        As[dq * 8 + 2][r] = a0.z; As[dq * 8 + 3][r] = a0.w;
        As[dq * 8 + 4][r] = a1.x; As[dq * 8 + 5][r] = a1.y;
        As[dq * 8 + 6][r] = a1.z; As[dq * 8 + 7][r] = a1.w;
        Bs[dq * 8 + 0][r] = b0.x; Bs[dq * 8 + 1][r] = b0.y;
        Bs[dq * 8 + 2][r] = b0.z; Bs[dq * 8 + 3][r] = b0.w;
        Bs[dq * 8 + 4][r] = b1.x; Bs[dq * 8 + 5][r] = b1.y;
        Bs[dq * 8 + 6][r] = b1.z; Bs[dq * 8 + 7][r] = b1.w;
        __syncthreads();
        #pragma unroll
        for (int k = 0; k < 32; k++) {
            float4 a = *(const float4*)&As[k][ty * 4];
            float4 b = *(const float4*)&Bs[k][tx * 4];
            float ai[4] = {a.x, a.y, a.z, a.w};
            float bj[4] = {b.x, b.y, b.z, b.w};
            #pragma unroll
            for (int i = 0; i < 4; i++)
                #pragma unroll
                for (int j = 0; j < 4; j++) acc[i][j] += ai[i] * bj[j];
        }
        __syncthreads();
    }
    #pragma unroll
    for (int i = 0; i < 4; i++)
        *(float4*)(g_Mraw + (size_t)(bm + ty * 4 + i) * CDIM + bn + tx * 4) =
            make_float4(acc[i][0], acc[i][1], acc[i][2], acc[i][3]);
}

// ---------------- K1b: per-c derived vectors ----------------
__global__ void prepB_kernel(const float* __restrict__ Wq, const float* __restrict__ Wk,
                             const float* __restrict__ bq, const float* __restrict__ bk,
                             const float* __restrict__ kg, const float* __restrict__ kb) {
    const int c = blockIdx.x;
    const int t = threadIdx.x;
    __shared__ float s8[8];
    float mraw = g_Mraw[(size_t)c * CDIM + t];
    g_M2[(size_t)c * CDIM + t] = mraw * kg[t];
    float mb = blockSum256(mraw * kb[t], s8);
    float u  = blockSum256(t < DDIM ? Wq[(size_t)c * DDIM + t] * bk[t] : 0.f, s8);
    float bv = blockSum256(t < DDIM ? Wk[(size_t)c * DDIM + t] * bq[t] : 0.f, s8);
    if (t == 0) {
        g_rowvec[c] = mb + u;
        g_bv[c] = bv;
        g_bv2[c] = bv * kg[c];
    }
}

// ---------------- K2: stats (warp/row, 8 rows/block) + g_const (last block) ----------------
__global__ void __launch_bounds__(256)
stats_kernel(const float* __restrict__ x, const float* __restrict__ Wk,
             const float* __restrict__ kb, const float* __restrict__ bk,
             const float* __restrict__ bq) {
    const int bid = blockIdx.x;
    const int tid = threadIdx.x;
    if (bid < ROWS / 8) {
        const int w = tid >> 5, l = tid & 31;
        const int row = bid * 8 + w;
        const float* xr = x + (size_t)row * CDIM + l * 8;
        float4 xa = *(const float4*)(xr);
        float4 xb = *(const float4*)(xr + 4);
        float s1 = xa.x + xa.y + xa.z + xa.w + xb.x + xb.y + xb.z + xb.w;
        float s2 = xa.x*xa.x + xa.y*xa.y + xa.z*xa.z + xa.w*xa.w
                 + xb.x*xb.x + xb.y*xb.y + xb.z*xb.z + xb.w*xb.w;
        #pragma unroll
        for (int o = 16; o; o >>= 1) {
            s1 += __shfl_xor_sync(0xffffffffu, s1, o);
            s2 += __shfl_xor_sync(0xffffffffu, s2, o);
        }
        if (l == 0) {
            float mu = s1 * (1.f / CDIM);
            float var = s2 * (1.f / CDIM) - mu * mu;
            g_stat[row] = make_float2(mu, rsqrtf(var + LN_EPS));
        }
    } else {
        // g_const = bq . (Wk^T kb + bk)
        __shared__ float s8[8];
        float acc = 0.f;
        if (tid < DDIM) {
            for (int c = 0; c < CDIM; c++) acc += Wk[(size_t)c * DDIM + tid] * kb[c];
            acc = (acc + bk[tid]) * bq[tid];
        }
        float tot = blockSum256(acc, s8);
        if (tid == 0) g_const[0] = tot;
    }
}

// ---------------- K3: 3xTF32 tensor-core GEMM  w = LN(x) @ M2 + bv2 ; also Bc ----------------
// Block tile 64(M) x 128(N), K-slab 16, 8 warps (2x4), warp tile 32x32.
// A/B split into tf32 hi+lo; acc = Ah*Bh + Ah*Bl + Al*Bh (fp32-equivalent).
__global__ void __launch_bounds__(256)
gemm_kernel(const float* __restrict__ x,
            const float* __restrict__ qg, const float* __restrict__ qb) {
    __shared__ __align__(16) float buf[8448];   // 33 KB, multi-purpose
    float* As_hi = buf;              // [64][20]
    float* As_lo = buf + 1280;       // [64][20]
    float* Bs_hi = buf + 2560;       // [16][132]
    float* Bs_lo = buf + 4672;       // [16][132]
    float* Cs    = buf;              // [64][132] (reused after main loop)

    const int bm = blockIdx.y * 64;
    const int bn = blockIdx.x * 128;
    const int tid = threadIdx.x;
    const int warp = tid >> 5;
    const int wm = warp >> 2;        // 0..1  (M)
    const int wn = warp & 3;         // 0..3  (N)

    // A staging: row r (0..63), k-quad kq
    const int r  = tid >> 2;
    const int kq = (tid & 3) * 4;
    // B staging: k-row kr (0..15), col-octet cq
    const int kr = tid >> 4;
    const int cq = (tid & 15) * 8;

    const float2 st = g_stat[bm + r];
    const float* xp = x + (size_t)(bm + r) * CDIM + kq;

    wmma::fragment<wmma::accumulator, 16, 16, 8, float> c[2][2];
    #pragma unroll
    for (int mi = 0; mi < 2; mi++)
        #pragma unroll
        for (int nj = 0; nj < 2; nj++) wmma::fill_fragment(c[mi][nj], 0.f);

    float bcacc = 0.f;

    for (int k0 = 0; k0 < CDIM; k0 += 16) {
        // ---- stage A with fused LayerNorm + hi/lo split ----
        {
            float4 xa = *(const float4*)(xp + k0);
            float4 gq = *(const float4*)(qg + k0 + kq);
            float4 gb = *(const float4*)(qb + k0 + kq);
            float4 rv = *(const float4*)(g_rowvec + k0 + kq);
            float l0 = fmaf((xa.x - st.x) * st.y, gq.x, gb.x);
            float l1 = fmaf((xa.y - st.x) * st.y, gq.y, gb.y);
            float l2 = fmaf((xa.z - st.x) * st.y, gq.z, gb.z);
            float l3 = fmaf((xa.w - st.x) * st.y, gq.w, gb.w);
            bcacc += l0 * rv.x + l1 * rv.y + l2 * rv.z + l3 * rv.w;
            float h0 = tf32_rna(l0), h1 = tf32_rna(l1);
            float h2 = tf32_rna(l2), h3 = tf32_rna(l3);
            float* ah = As_hi + r * 20 + kq;
            float* al = As_lo + r * 20 + kq;
            ah[0] = h0; ah[1] = h1; ah[2] = h2; ah[3] = h3;
            al[0] = tf32_rna(l0 - h0); al[1] = tf32_rna(l1 - h1);
            al[2] = tf32_rna(l2 - h2); al[3] = tf32_rna(l3 - h3);
        }
        // ---- stage B + hi/lo split ----
        {
            const float* bp = g_M2 + (size_t)(k0 + kr) * CDIM + bn + cq;
            float4 b0 = *(const float4*)(bp);
            float4 b1 = *(const float4*)(bp + 4);
            float* bh = Bs_hi + kr * 132 + cq;
            float* bl = Bs_lo + kr * 132 + cq;
            float v[8] = {b0.x, b0.y, b0.z, b0.w, b1.x, b1.y, b1.z, b1.w};
            #pragma unroll
            for (int i = 0; i < 8; i++) {
                float h = tf32_rna(v[i]);
                bh[i] = h;
                bl[i] = tf32_rna(v[i] - h);
            }
        }
        __syncthreads();

        #pragma unroll
        for (int ks = 0; ks < 16; ks += 8) {
            wmma::fragment<wmma::matrix_a, 16, 16, 8, wmma::precision::tf32, wmma::row_major> ah[2], al[2];
            wmma::fragment<wmma::matrix_b, 16, 16, 8, wmma::precision::tf32, wmma::row_major> bh[2], bl[2];
            #pragma unroll
            for (int mi = 0; mi < 2; mi++) {
                wmma::load_matrix_sync(ah[mi], As_hi + (wm * 32 + mi * 16) * 20 + ks, 20);
                wmma::load_matrix_sync(al[mi], As_lo + (wm * 32 + mi * 16) * 20 + ks, 20);
            }
            #pragma unroll
            for (int nj = 0; nj < 2; nj++) {
                wmma::load_matrix_sync(bh[nj], Bs_hi + ks * 132 + wn * 32 + nj * 16, 132);
                wmma::load_matrix_sync(bl[nj], Bs_lo + ks * 132 + wn * 32 + nj * 16, 132);
            }
            #pragma unroll
            for (int mi = 0; mi < 2; mi++)
                #pragma unroll
                for (int nj = 0; nj < 2; nj++) {
                    wmma::mma_sync(c[mi][nj], ah[mi], bh[nj], c[mi][nj]);
                    wmma::mma_sync(c[mi][nj], ah[mi], bl[nj], c[mi][nj]);
                    wmma::mma_sync(c[mi][nj], al[mi], bh[nj], c[mi][nj]);
                }
        }
        __syncthreads();
    }

    // Bc: reduce over the 4 kq-lanes sharing row r (adjacent lanes)
    bcacc += __shfl_xor_sync(0xffffffffu, bcacc, 1);
    bcacc += __shfl_xor_sync(0xffffffffu, bcacc, 2);
    if ((tid & 3) == 0 && blockIdx.x == 0)
        g_Bc[bm + r] = bcacc + g_const[0];

    // epilogue: c frags -> smem -> +bias -> g_w (coalesced float4)
    #pragma unroll
    for (int mi = 0; mi < 2; mi++)
        #pragma unroll
        for (int nj = 0; nj < 2; nj++)
            wmma::store_matrix_sync(Cs + (wm * 32 + mi * 16) * 132 + wn * 32 + nj * 16,
                                    c[mi][nj], 132, wmma::mem_row_major);
    __syncthreads();

    {
        const int r2 = tid >> 2;
        const int c0 = (tid & 3) * 32;
        float* dst = g_w + (size_t)(bm + r2) * CDIM + bn + c0;
        const float* src = Cs + r2 * 132 + c0;
        #pragma unroll
        for (int j = 0; j < 8; j++) {
            float4 cv = *(const float4*)(src + j * 4);
            float4 bv = *(const float4*)(g_bv2 + bn + c0 + j * 4);
            *(float4*)(dst + j * 4) =
                make_float4(cv.x + bv.x, cv.y + bv.y, cv.z + bv.z, cv.w + bv.w);
        }
    }
}

// ---------------- K4: main streaming pass over y + softmax + z-sum ----------------
__global__ void attn_kernel(const float* __restrict__ y, const float* __restrict__ z,
                            float* __restrict__ out) {
    const int row = blockIdx.x;    // b*M + m
    const int tid = threadIdx.x;   // 256 threads
    __shared__ __align__(16) float sw[CDIM];
    __shared__ float s8[8];
    __shared__ float sdot[NDIM];

    float wv = g_w[(size_t)row * CDIM + tid];
    sw[tid] = wv;
    float G = blockSum256(wv, s8);   // includes syncthreads -> sw visible

    const int n = tid >> 3, t8 = tid & 7;
    const float* yr = y + ((size_t)row * NDIM + n) * CDIM;
    float S1 = 0.f, S2 = 0.f, S3 = 0.f;
    #pragma unroll
    for (int j = 0; j < 8; j++) {
        const int col = j * 32 + t8 * 4;
        float4 yv = __ldcs((const float4*)(yr + col));
        float4 w4 = *(const float4*)(sw + col);
        S1 += yv.x + yv.y + yv.z + yv.w;
        S2 += yv.x * yv.x + yv.y * yv.y + yv.z * yv.z + yv.w * yv.w;
        S3 += yv.x * w4.x + yv.y * w4.y + yv.z * w4.z + yv.w * w4.w;
    }
    #pragma unroll
    for (int o = 4; o; o >>= 1) {
        S1 += __shfl_down_sync(0xffffffffu, S1, o);
        S2 += __shfl_down_sync(0xffffffffu, S2, o);
        S3 += __shfl_down_sync(0xffffffffu, S3, o);
    }
    if (t8 == 0) {
        float mu = S1 * (1.f / CDIM);
        float var = S2 * (1.f / CDIM) - mu * mu;
        float rs = rsqrtf(var + LN_EPS);
        sdot[n] = SCALE * (rs * (S3 - mu * G) + g_Bc[row]);
    }
    __syncthreads();
    if (tid < NDIM) {
        float v = sdot[tid];
        float m = v;
        #pragma unroll
        for (int o = 16; o; o >>= 1) m = fmaxf(m, __shfl_xor_sync(0xffffffffu, m, o));
        float e = expf(v - m);
        float zb = z[(size_t)row * NDIM + tid];
        float se = e, sez = e * zb;
        #pragma unroll
        for (int o = 16; o; o >>= 1) {
            se += __shfl_xor_sync(0xffffffffu, se, o);
            sez += __shfl_xor_sync(0xffffffffu, sez, o);
        }
        if (tid == 0) out[row] = sez / se;
    }
}

// ---------------- launch ----------------
extern "C" void kernel_launch(void* const* d_in, const int* in_sizes, int n_in,
                              void* d_out, int out_size) {
    const float* x  = (const float*)d_in[0];
    const float* y  = (const float*)d_in[1];
    const float* z  = (const float*)d_in[2];
    const float* qg = (const float*)d_in[3];
    const float* qb = (const float*)d_in[4];
    const float* Wq = (const float*)d_in[5];
    const float* bq = (const float*)d_in[6];
    const float* kg = (const float*)d_in[7];
    const float* kb = (const float*)d_in[8];
    const float* Wk = (const float*)d_in[9];
    const float* bk = (const float*)d_in[10];
    float* out = (float*)d_out;

    stats_kernel<<<ROWS / 8 + 1, 256>>>(x, Wk, kb, bk, bq);
    prepA_kernel<<<dim3(4, 4), 256>>>(Wq, Wk);
    prepB_kernel<<<CDIM, 256>>>(Wq, Wk, bq, bk, kg, kb);
    gemm_kernel<<<dim3(2, ROWS / 64), 256>>>(x, qg, qb);
    attn_kernel<<<ROWS, 256>>>(y, z, out);
}

// round 10
// speedup vs baseline: 1.7145x; 1.3181x over previous
#include <cuda_runtime.h>
#include <cuda_bf16.h>
#include <cstdint>

// Problem constants (fixed by setup_inputs)
#define BATCH 4
#define MDIM 4096
#define NDIM 32
#define CDIM 256
#define DDIM 128
#define ROWS (BATCH * MDIM)        // 16384
#define LN_EPS 1e-5f
#define SCALE 0.08838834764831845f // 1/sqrt(128)

// ---------------- scratch (device globals, no allocation) ----------------
__device__ __align__(16) float g_Mraw[CDIM * CDIM]; // Wq @ Wk^T
__device__ __align__(16) float g_M3[CDIM * CDIM];   // qg[k] * Mraw[k][c] * kg[c]
__device__ __align__(16) float g_P[CDIM];           // kg[c] * (qb @ Mraw)[c]
__device__ __align__(16) float g_Q[CDIM];           // kg[c] * (qg @ Mraw)[c]
__device__ __align__(16) float g_bv2[CDIM];         // kg[c] * (Wk[c,:]·bq)
__device__ __align__(16) float g_rowvec[CDIM];      // mb[c] + u[c]
__device__ __align__(16) float g_e[CDIM];           // qg ⊙ rowvec
__device__ float g_const[1];                        // bq·(Wk^T kb + bk)
__device__ __align__(16) float g_w[ROWS * CDIM];    // per-row weight vectors
__device__ float g_Bc[ROWS];                        // per-row scalar bias

// ---------------- helpers ----------------
__device__ __forceinline__ float blockSum256(float v, float* s8) {
    #pragma unroll
    for (int o = 16; o; o >>= 1) v += __shfl_xor_sync(0xffffffffu, v, o);
    __syncthreads();
    if ((threadIdx.x & 31) == 0) s8[threadIdx.x >> 5] = v;
    __syncthreads();
    float tot = 0.f;
    #pragma unroll
    for (int i = 0; i < 8; i++) tot += s8[i];
    return tot;
}

#define FMA2(d, a, b) \
    asm("fma.rn.f32x2 %0, %1, %2, %0;" : "+l"(d) : "l"(a), "l"(b))
#define PACK2(out, lo, hi) \
    asm("mov.b64 %0, {%1, %2};" : "=l"(out) : "r"(__float_as_uint(lo)), "r"(__float_as_uint(hi)))

__device__ __forceinline__ float2 unpack2(unsigned long long v) {
    unsigned int lo, hi;
    asm("mov.b64 {%0, %1}, %2;" : "=r"(lo), "=r"(hi) : "l"(v));
    return make_float2(__uint_as_float(lo), __uint_as_float(hi));
}

// ---------------- K1a: Mraw = Wq(256x128) @ Wk^T(128x256), tiled ----------------
__global__ void prepA_kernel(const float* __restrict__ Wq, const float* __restrict__ Wk) {
    __shared__ float As[32][68];
    __shared__ float Bs[32][68];
    const int bm = blockIdx.y * 64;
    const int bn = blockIdx.x * 64;
    const int tid = threadIdx.x;
    const int tx = tid & 15, ty = tid >> 4;
    const int r = tid >> 2, dq = tid & 3;

    float acc[4][4];
    #pragma unroll
    for (int i = 0; i < 4; i++)
        #pragma unroll
        for (int j = 0; j < 4; j++) acc[i][j] = 0.f;

    for (int k0 = 0; k0 < DDIM; k0 += 32) {
        float4 a0 = *(const float4*)(Wq + (size_t)(bm + r) * DDIM + k0 + dq * 8);
        float4 a1 = *(const float4*)(Wq + (size_t)(bm + r) * DDIM + k0 + dq * 8 + 4);
        float4 b0 = *(const float4*)(Wk + (size_t)(bn + r) * DDIM + k0 + dq * 8);
        float4 b1 = *(const float4*)(Wk + (size_t)(bn + r) * DDIM + k0 + dq * 8 + 4);
        As[dq * 8 + 0][r] = a0.x; As[dq * 8 + 1][r] = a0.y;
        As[dq * 8 + 2][r] = a0.z; As[dq * 8 + 3][r] = a0.w;
        As[dq * 8 + 4][r] = a1.x; As[dq * 8 + 5][r] = a1.y;
        As[dq * 8 + 6][r] = a1.z; As[dq * 8 + 7][r] = a1.w;
        Bs[dq * 8 + 0][r] = b0.x; Bs[dq * 8 + 1][r] = b0.y;
        Bs[dq * 8 + 2][r] = b0.z; Bs[dq * 8 + 3][r] = b0.w;
        Bs[dq * 8 + 4][r] = b1.x; Bs[dq * 8 + 5][r] = b1.y;
        Bs[dq * 8 + 6][r] = b1.z; Bs[dq * 8 + 7][r] = b1.w;
        __syncthreads();
        #pragma unroll
        for (int k = 0; k < 32; k++) {
            float4 a = *(const float4*)&As[k][ty * 4];
            float4 b = *(const float4*)&Bs[k][tx * 4];
            float ai[4] = {a.x, a.y, a.z, a.w};
            float bj[4] = {b.x, b.y, b.z, b.w};
            #pragma unroll
            for (int i = 0; i < 4; i++)
                #pragma unroll
                for (int j = 0; j < 4; j++) acc[i][j] += ai[i] * bj[j];
        }
        __syncthreads();
    }
    #pragma unroll
    for (int i = 0; i < 4; i++)
        *(float4*)(g_Mraw + (size_t)(bm + ty * 4 + i) * CDIM + bn + tx * 4) =
            make_float4(acc[i][0], acc[i][1], acc[i][2], acc[i][3]);
}

// ---------------- K1b: derived vectors; blocks 0..255 per-row, 256: P/Q, 257: const ----------------
__global__ void prepB_kernel(const float* __restrict__ Wq, const float* __restrict__ Wk,
                             const float* __restrict__ bq, const float* __restrict__ bk,
                             const float* __restrict__ kg, const float* __restrict__ kb,
                             const float* __restrict__ qg, const float* __restrict__ qb) {
    const int c = blockIdx.x;
    const int t = threadIdx.x;
    __shared__ float s8[8];
    __shared__ float sA[CDIM], sB[CDIM];

    if (c < CDIM) {
        float mraw = g_Mraw[(size_t)c * CDIM + t];
        g_M3[(size_t)c * CDIM + t] = mraw * kg[t] * qg[c];
        float mb = blockSum256(mraw * kb[t], s8);
        float u  = blockSum256(t < DDIM ? Wq[(size_t)c * DDIM + t] * bk[t] : 0.f, s8);
        float bv = blockSum256(t < DDIM ? Wk[(size_t)c * DDIM + t] * bq[t] : 0.f, s8);
        if (t == 0) {
            float rv = mb + u;
            g_rowvec[c] = rv;
            g_e[c] = qg[c] * rv;
            g_bv2[c] = bv * kg[c];
        }
    } else if (c == CDIM) {
        // P[t] = kg[t] * sum_k qb[k]*Mraw[k][t];  Q[t] = kg[t] * sum_k qg[k]*Mraw[k][t]
        sA[t] = qb[t];
        sB[t] = qg[t];
        __syncthreads();
        float accP = 0.f, accQ = 0.f;
        for (int k = 0; k < CDIM; k++) {
            float m = g_Mraw[(size_t)k * CDIM + t];   // coalesced over t
            accP += sA[k] * m;
            accQ += sB[k] * m;
        }
        float kgt = kg[t];
        g_P[t] = kgt * accP;
        g_Q[t] = kgt * accQ;
    } else {
        // g_const = bq . (Wk^T kb + bk)
        float acc = 0.f;
        if (t < DDIM) {
            for (int c2 = 0; c2 < CDIM; c2++) acc += Wk[(size_t)c2 * DDIM + t] * kb[c2];
            acc = (acc + bk[t]) * bq[t];
        }
        float tot = blockSum256(acc, s8);
        if (t == 0) g_const[0] = tot;
    }
}

// ---------------- K2: GEMM  acc = x @ M3 ; LN folded into prologue stats + epilogue ----------------
// 64(M) x 128(N) tile, BK=32, 256 threads, 4x8 per thread, packed f32x2 FMAs, reg prefetch.
__global__ void __launch_bounds__(256)
gemm_kernel(const float* __restrict__ x, const float* __restrict__ qb) {
    __shared__ __align__(16) float As[32][68];   // [k][m]
    __shared__ __align__(16) float Bs[32][132];  // [k][n]
    __shared__ float s_mu[64], s_rs[64];
    __shared__ __align__(16) float s_e[CDIM];
    __shared__ float s8[8];

    const int bm = blockIdx.y * 64;
    const int bn = blockIdx.x * 128;
    const int tid = threadIdx.x;

    // ---- phase 0: e into smem; E, F block scalars ----
    float ev = g_e[tid];
    s_e[tid] = ev;
    float E = blockSum256(ev, s8);
    float F = blockSum256(qb[tid] * g_rowvec[tid], s8);

    // ---- phase 1: per-row stats (warp w -> rows w*8..w*8+7, 4 lanes/row) ----
    {
        const int w = tid >> 5, l = tid & 31;
        const int srow = w * 8 + (l >> 2);
        const int seg = l & 3;
        const float* xr = x + (size_t)(bm + srow) * CDIM + seg * 4;
        float s1 = 0.f, s2 = 0.f, s3 = 0.f;
        #pragma unroll
        for (int j = 0; j < 16; j++) {
            float4 v = *(const float4*)(xr + j * 16);
            const float* ep = s_e + seg * 4 + j * 16;
            s1 += v.x + v.y + v.z + v.w;
            s2 += v.x * v.x + v.y * v.y + v.z * v.z + v.w * v.w;
            s3 += v.x * ep[0] + v.y * ep[1] + v.z * ep[2] + v.w * ep[3];
        }
        #pragma unroll
        for (int o = 1; o <= 2; o <<= 1) {
            s1 += __shfl_xor_sync(0xffffffffu, s1, o);
            s2 += __shfl_xor_sync(0xffffffffu, s2, o);
            s3 += __shfl_xor_sync(0xffffffffu, s3, o);
        }
        if (seg == 0) {
            float mu = s1 * (1.f / CDIM);
            float var = s2 * (1.f / CDIM) - mu * mu;
            float rs = rsqrtf(var + LN_EPS);
            s_mu[srow] = mu;
            s_rs[srow] = rs;
            if (blockIdx.x == 0)
                g_Bc[bm + srow] = rs * (s3 - mu * E) + F + g_const[0];
        }
    }
    __syncthreads();

    // ---- main loop: raw x @ M3, BK=32, register-prefetch double buffer ----
    const int ar = tid >> 2, aq = tid & 3;          // A staging
    const int kr = tid >> 4, cq = tid & 15;         // B staging
    const int tx = tid & 15, ty = tid >> 4;         // compute mapping

    const float* xp  = x + (size_t)(bm + ar) * CDIM + aq * 4;
    const float* bp0 = g_M3 + (size_t)kr * CDIM + bn + cq * 8;
    const float* bp1 = g_M3 + (size_t)(kr + 16) * CDIM + bn + cq * 8;

    unsigned long long acc[4][4];
    #pragma unroll
    for (int i = 0; i < 4; i++)
        #pragma unroll
        for (int j = 0; j < 4; j++) acc[i][j] = 0ull;

    float4 xa0 = *(const float4*)(xp);
    float4 xa1 = *(const float4*)(xp + 16);
    float4 b00 = *(const float4*)(bp0);
    float4 b01 = *(const float4*)(bp0 + 4);
    float4 b10 = *(const float4*)(bp1);
    float4 b11 = *(const float4*)(bp1 + 4);

    for (int k0 = 0; k0 < CDIM; k0 += 32) {
        As[aq * 4 + 0][ar] = xa0.x; As[aq * 4 + 1][ar] = xa0.y;
        As[aq * 4 + 2][ar] = xa0.z; As[aq * 4 + 3][ar] = xa0.w;
        As[16 + aq * 4 + 0][ar] = xa1.x; As[16 + aq * 4 + 1][ar] = xa1.y;
        As[16 + aq * 4 + 2][ar] = xa1.z; As[16 + aq * 4 + 3][ar] = xa1.w;
        *(float4*)&Bs[kr][cq * 8]          = b00;
        *(float4*)&Bs[kr][cq * 8 + 4]      = b01;
        *(float4*)&Bs[kr + 16][cq * 8]     = b10;
        *(float4*)&Bs[kr + 16][cq * 8 + 4] = b11;
        __syncthreads();

        if (k0 + 32 < CDIM) {
            xa0 = *(const float4*)(xp + k0 + 32);
            xa1 = *(const float4*)(xp + k0 + 48);
            b00 = *(const float4*)(bp0 + (size_t)(k0 + 32) * CDIM);
            b01 = *(const float4*)(bp0 + (size_t)(k0 + 32) * CDIM + 4);
            b10 = *(const float4*)(bp1 + (size_t)(k0 + 32) * CDIM);
            b11 = *(const float4*)(bp1 + (size_t)(k0 + 32) * CDIM + 4);
        }

        #pragma unroll
        for (int k = 0; k < 32; k++) {
            float4 a = *(const float4*)&As[k][ty * 4];
            const unsigned long long* p0 = (const unsigned long long*)&Bs[k][tx * 4];
            const unsigned long long* p1 = (const unsigned long long*)&Bs[k][64 + tx * 4];
            unsigned long long b0 = p0[0], b1 = p0[1], b2 = p1[0], b3 = p1[1];
            float av[4] = {a.x, a.y, a.z, a.w};
            #pragma unroll
            for (int i = 0; i < 4; i++) {
                unsigned long long ad;
                PACK2(ad, av[i], av[i]);
                FMA2(acc[i][0], ad, b0);
                FMA2(acc[i][1], ad, b1);
                FMA2(acc[i][2], ad, b2);
                FMA2(acc[i][3], ad, b3);
            }
        }
        __syncthreads();
    }

    // ---- epilogue: w = rs*acc + P - rs*mu*Q + bv2 ----
    float4 P0 = *(const float4*)(g_P + bn + tx * 4);
    float4 P1 = *(const float4*)(g_P + bn + 64 + tx * 4);
    float4 Q0 = *(const float4*)(g_Q + bn + tx * 4);
    float4 Q1 = *(const float4*)(g_Q + bn + 64 + tx * 4);
    float4 V0 = *(const float4*)(g_bv2 + bn + tx * 4);
    float4 V1 = *(const float4*)(g_bv2 + bn + 64 + tx * 4);
    #pragma unroll
    for (int i = 0; i < 4; i++) {
        const int rt_ = ty * 4 + i;
        const float rs = s_rs[rt_];
        const float rm = rs * s_mu[rt_];
        const int row = bm + rt_;
        float2 p0 = unpack2(acc[i][0]);
        float2 p1 = unpack2(acc[i][1]);
        float2 p2 = unpack2(acc[i][2]);
        float2 p3 = unpack2(acc[i][3]);
        *(float4*)(g_w + (size_t)row * CDIM + bn + tx * 4) = make_float4(
            fmaf(rs, p0.x, P0.x - rm * Q0.x + V0.x),
            fmaf(rs, p0.y, P0.y - rm * Q0.y + V0.y),
            fmaf(rs, p1.x, P0.z - rm * Q0.z + V0.z),
            fmaf(rs, p1.y, P0.w - rm * Q0.w + V0.w));
        *(float4*)(g_w + (size_t)row * CDIM + bn + 64 + tx * 4) = make_float4(
            fmaf(rs, p2.x, P1.x - rm * Q1.x + V1.x),
            fmaf(rs, p2.y, P1.y - rm * Q1.y + V1.y),
            fmaf(rs, p3.x, P1.z - rm * Q1.z + V1.z),
            fmaf(rs, p3.y, P1.w - rm * Q1.w + V1.w));
    }
}

// ---------------- K3: main streaming pass over y + softmax + z-sum ----------------
__global__ void attn_kernel(const float* __restrict__ y, const float* __restrict__ z,
                            float* __restrict__ out) {
    const int row = blockIdx.x;    // b*M + m
    const int tid = threadIdx.x;   // 256 threads
    __shared__ __align__(16) float sw[CDIM];
    __shared__ float s8[8];
    __shared__ float sdot[NDIM];

    float wv = g_w[(size_t)row * CDIM + tid];
    sw[tid] = wv;
    float G = blockSum256(wv, s8);   // includes syncthreads -> sw visible

    const int n = tid >> 3, t8 = tid & 7;
    const float* yr = y + ((size_t)row * NDIM + n) * CDIM;
    float S1 = 0.f, S2 = 0.f, S3 = 0.f;
    #pragma unroll
    for (int j = 0; j < 8; j++) {
        const int col = j * 32 + t8 * 4;
        float4 yv = __ldcs((const float4*)(yr + col));
        float4 w4 = *(const float4*)(sw + col);
        S1 += yv.x + yv.y + yv.z + yv.w;
        S2 += yv.x * yv.x + yv.y * yv.y + yv.z * yv.z + yv.w * yv.w;
        S3 += yv.x * w4.x + yv.y * w4.y + yv.z * w4.z + yv.w * w4.w;
    }
    #pragma unroll
    for (int o = 4; o; o >>= 1) {
        S1 += __shfl_down_sync(0xffffffffu, S1, o);
        S2 += __shfl_down_sync(0xffffffffu, S2, o);
        S3 += __shfl_down_sync(0xffffffffu, S3, o);
    }
    if (t8 == 0) {
        float mu = S1 * (1.f / CDIM);
        float var = S2 * (1.f / CDIM) - mu * mu;
        float rs = rsqrtf(var + LN_EPS);
        sdot[n] = SCALE * (rs * (S3 - mu * G) + g_Bc[row]);
    }
    __syncthreads();
    if (tid < NDIM) {
        float v = sdot[tid];
        float m = v;
        #pragma unroll
        for (int o = 16; o; o >>= 1) m = fmaxf(m, __shfl_xor_sync(0xffffffffu, m, o));
        float e = expf(v - m);
        float zb = z[(size_t)row * NDIM + tid];
        float se = e, sez = e * zb;
        #pragma unroll
        for (int o = 16; o; o >>= 1) {
            se += __shfl_xor_sync(0xffffffffu, se, o);
            sez += __shfl_xor_sync(0xffffffffu, sez, o);
        }
        if (tid == 0) out[row] = sez / se;
    }
}

// ---------------- launch ----------------
extern "C" void kernel_launch(void* const* d_in, const int* in_sizes, int n_in,
                              void* d_out, int out_size) {
    const float* x  = (const float*)d_in[0];
    const float* y  = (const float*)d_in[1];
    const float* z  = (const float*)d_in[2];
    const float* qg = (const float*)d_in[3];
    const float* qb = (const float*)d_in[4];
    const float* Wq = (const float*)d_in[5];
    const float* bq = (const float*)d_in[6];
    const float* kg = (const float*)d_in[7];
    const float* kb = (const float*)d_in[8];
    const float* Wk = (const float*)d_in[9];
    const float* bk = (const float*)d_in[10];
    float* out = (float*)d_out;

    prepA_kernel<<<dim3(4, 4), 256>>>(Wq, Wk);
    prepB_kernel<<<CDIM + 2, 256>>>(Wq, Wk, bq, bk, kg, kb, qg, qb);
    gemm_kernel<<<dim3(2, ROWS / 64), 256>>>(x, qb);
    attn_kernel<<<ROWS, 256>>>(y, z, out);
}

// round 11
// speedup vs baseline: 1.8248x; 1.0643x over previous
#include <cuda_runtime.h>
#include <cuda_bf16.h>
#include <cstdint>

// Problem constants (fixed by setup_inputs)
#define BATCH 4
#define MDIM 4096
#define NDIM 32
#define CDIM 256
#define DDIM 128
#define ROWS (BATCH * MDIM)        // 16384
#define LN_EPS 1e-5f
#define SCALE 0.08838834764831845f // 1/sqrt(128)

// ---------------- scratch (device globals, no allocation) ----------------
__device__ __align__(16) float g_Mraw[CDIM * CDIM]; // Wq @ Wk^T
__device__ __align__(16) float g_M3[CDIM * CDIM];   // qg[k] * Mraw[k][c] * kg[c]
__device__ __align__(16) float g_P[CDIM];           // kg[c] * (qb @ Mraw)[c]
__device__ __align__(16) float g_Q[CDIM];           // kg[c] * (qg @ Mraw)[c]
__device__ __align__(16) float g_bv2[CDIM];         // kg[c] * (Wk[c,:]·bq)
__device__ __align__(16) float g_rowvec[CDIM];      // mb[c] + u[c]
__device__ __align__(16) float g_e[CDIM];           // qg ⊙ rowvec
__device__ float g_const[1];                        // bq·(Wk^T kb + bk)
__device__ __align__(16) float g_w[ROWS * CDIM];    // per-row weight vectors
__device__ float g_Bc[ROWS];                        // per-row scalar bias

// ---------------- helpers ----------------
__device__ __forceinline__ float blockSum256(float v, float* s8) {
    #pragma unroll
    for (int o = 16; o; o >>= 1) v += __shfl_xor_sync(0xffffffffu, v, o);
    __syncthreads();
    if ((threadIdx.x & 31) == 0) s8[threadIdx.x >> 5] = v;
    __syncthreads();
    float tot = 0.f;
    #pragma unroll
    for (int i = 0; i < 8; i++) tot += s8[i];
    return tot;
}

#define FMA2(d, a, b) \
    asm("fma.rn.f32x2 %0, %1, %2, %0;" : "+l"(d) : "l"(a), "l"(b))
#define PACK2(out, lo, hi) \
    asm("mov.b64 %0, {%1, %2};" : "=l"(out) : "r"(__float_as_uint(lo)), "r"(__float_as_uint(hi)))

__device__ __forceinline__ float2 unpack2(unsigned long long v) {
    unsigned int lo, hi;
    asm("mov.b64 {%0, %1}, %2;" : "=r"(lo), "=r"(hi) : "l"(v));
    return make_float2(__uint_as_float(lo), __uint_as_float(hi));
}

// ---------------- K1a: Mraw = Wq(256x128) @ Wk^T(128x256), tiled ----------------
__global__ void prepA_kernel(const float* __restrict__ Wq, const float* __restrict__ Wk) {
    __shared__ float As[32][68];
    __shared__ float Bs[32][68];
    const int bm = blockIdx.y * 64;
    const int bn = blockIdx.x * 64;
    const int tid = threadIdx.x;
    const int tx = tid & 15, ty = tid >> 4;
    const int r = tid >> 2, dq = tid & 3;

    float acc[4][4];
    #pragma unroll
    for (int i = 0; i < 4; i++)
        #pragma unroll
        for (int j = 0; j < 4; j++) acc[i][j] = 0.f;

    for (int k0 = 0; k0 < DDIM; k0 += 32) {
        float4 a0 = *(const float4*)(Wq + (size_t)(bm + r) * DDIM + k0 + dq * 8);
        float4 a1 = *(const float4*)(Wq + (size_t)(bm + r) * DDIM + k0 + dq * 8 + 4);
        float4 b0 = *(const float4*)(Wk + (size_t)(bn + r) * DDIM + k0 + dq * 8);
        float4 b1 = *(const float4*)(Wk + (size_t)(bn + r) * DDIM + k0 + dq * 8 + 4);
        As[dq * 8 + 0][r] = a0.x; As[dq * 8 + 1][r] = a0.y;
        As[dq * 8 + 2][r] = a0.z; As[dq * 8 + 3][r] = a0.w;
        As[dq * 8 + 4][r] = a1.x; As[dq * 8 + 5][r] = a1.y;
        As[dq * 8 + 6][r] = a1.z; As[dq * 8 + 7][r] = a1.w;
        Bs[dq * 8 + 0][r] = b0.x; Bs[dq * 8 + 1][r] = b0.y;
        Bs[dq * 8 + 2][r] = b0.z; Bs[dq * 8 + 3][r] = b0.w;
        Bs[dq * 8 + 4][r] = b1.x; Bs[dq * 8 + 5][r] = b1.y;
        Bs[dq * 8 + 6][r] = b1.z; Bs[dq * 8 + 7][r] = b1.w;
        __syncthreads();
        #pragma unroll
        for (int k = 0; k < 32; k++) {
            float4 a = *(const float4*)&As[k][ty * 4];
            float4 b = *(const float4*)&Bs[k][tx * 4];
            float ai[4] = {a.x, a.y, a.z, a.w};
            float bj[4] = {b.x, b.y, b.z, b.w};
            #pragma unroll
            for (int i = 0; i < 4; i++)
                #pragma unroll
                for (int j = 0; j < 4; j++) acc[i][j] += ai[i] * bj[j];
        }
        __syncthreads();
    }
    #pragma unroll
    for (int i = 0; i < 4; i++)
        *(float4*)(g_Mraw + (size_t)(bm + ty * 4 + i) * CDIM + bn + tx * 4) =
            make_float4(acc[i][0], acc[i][1], acc[i][2], acc[i][3]);
}

// ---------------- K1b: derived vectors; blocks 0..255 per-row, 256: P/Q, 257: const ----------------
__global__ void prepB_kernel(const float* __restrict__ Wq, const float* __restrict__ Wk,
                             const float* __restrict__ bq, const float* __restrict__ bk,
                             const float* __restrict__ kg, const float* __restrict__ kb,
                             const float* __restrict__ qg, const float* __restrict__ qb) {
    const int c = blockIdx.x;
    const int t = threadIdx.x;
    __shared__ float s8[8];
    __shared__ float sA[CDIM], sB[CDIM];

    if (c < CDIM) {
        float mraw = g_Mraw[(size_t)c * CDIM + t];
        g_M3[(size_t)c * CDIM + t] = mraw * kg[t] * qg[c];
        float mb = blockSum256(mraw * kb[t], s8);
        float u  = blockSum256(t < DDIM ? Wq[(size_t)c * DDIM + t] * bk[t] : 0.f, s8);
        float bv = blockSum256(t < DDIM ? Wk[(size_t)c * DDIM + t] * bq[t] : 0.f, s8);
        if (t == 0) {
            float rv = mb + u;
            g_rowvec[c] = rv;
            g_e[c] = qg[c] * rv;
            g_bv2[c] = bv * kg[c];
        }
    } else if (c == CDIM) {
        sA[t] = qb[t];
        sB[t] = qg[t];
        __syncthreads();
        float accP = 0.f, accQ = 0.f;
        for (int k = 0; k < CDIM; k++) {
            float m = g_Mraw[(size_t)k * CDIM + t];   // coalesced over t
            accP += sA[k] * m;
            accQ += sB[k] * m;
        }
        float kgt = kg[t];
        g_P[t] = kgt * accP;
        g_Q[t] = kgt * accQ;
    } else {
        float acc = 0.f;
        if (t < DDIM) {
            for (int c2 = 0; c2 < CDIM; c2++) acc += Wk[(size_t)c2 * DDIM + t] * kb[c2];
            acc = (acc + bk[t]) * bq[t];
        }
        float tot = blockSum256(acc, s8);
        if (t == 0) g_const[0] = tot;
    }
}

// ---------------- K2: GEMM  acc = x @ M3 ; 128x128 tile, 8x8/thread, BK=16 ----------------
__global__ void __launch_bounds__(256, 2)
gemm_kernel(const float* __restrict__ x, const float* __restrict__ qb) {
    __shared__ __align__(16) float As[16][132];   // [k][m]  (132*4 = 528 B rows, 16B aligned)
    __shared__ __align__(16) float Bs[16][132];   // [k][n]
    __shared__ float s_mu[128], s_rs[128];
    __shared__ __align__(16) float s_e[CDIM];
    __shared__ float s8[8];

    const int bm = blockIdx.y * 128;
    const int bn = blockIdx.x * 128;
    const int tid = threadIdx.x;

    // ---- phase 0: e into smem; E, F block scalars ----
    float ev = g_e[tid];
    s_e[tid] = ev;
    float E = blockSum256(ev, s8);
    float F = blockSum256(qb[tid] * g_rowvec[tid], s8);

    // ---- phase 1: per-row stats, 2 threads per row (also warms x tile in L1) ----
    {
        const int ar = tid >> 1, half = tid & 1;
        const float* xr = x + (size_t)(bm + ar) * CDIM + half * 4;
        float s1 = 0.f, s2 = 0.f, s3 = 0.f;
        #pragma unroll
        for (int j = 0; j < 32; j++) {
            float4 v = *(const float4*)(xr + j * 8);
            const float* ep = s_e + half * 4 + j * 8;
            s1 += v.x + v.y + v.z + v.w;
            s2 += v.x * v.x + v.y * v.y + v.z * v.z + v.w * v.w;
            s3 += v.x * ep[0] + v.y * ep[1] + v.z * ep[2] + v.w * ep[3];
        }
        s1 += __shfl_xor_sync(0xffffffffu, s1, 1);
        s2 += __shfl_xor_sync(0xffffffffu, s2, 1);
        s3 += __shfl_xor_sync(0xffffffffu, s3, 1);
        if (half == 0) {
            float mu = s1 * (1.f / CDIM);
            float var = s2 * (1.f / CDIM) - mu * mu;
            float rs = rsqrtf(var + LN_EPS);
            s_mu[ar] = mu;
            s_rs[ar] = rs;
            if (blockIdx.x == 0)
                g_Bc[bm + ar] = rs * (s3 - mu * E) + F + g_const[0];
        }
    }
    __syncthreads();

    // ---- main loop: raw x @ M3, BK=16, register-prefetch, 8x8 per thread ----
    const int ar = tid >> 1, aq = tid & 1;          // A staging: row, k-octet
    const int bkr = tid >> 4, bcq = tid & 15;       // B staging: k-row, col-octet
    const int tx = tid & 15, ty = tid >> 4;         // compute mapping

    const float* xpa = x + (size_t)(bm + ar) * CDIM + aq * 8;
    const float* bp  = g_M3 + (size_t)bkr * CDIM + bn + bcq * 8;

    unsigned long long acc[8][4];
    #pragma unroll
    for (int i = 0; i < 8; i++)
        #pragma unroll
        for (int j = 0; j < 4; j++) acc[i][j] = 0ull;

    float4 a0 = *(const float4*)(xpa);
    float4 a1 = *(const float4*)(xpa + 4);
    float4 b0 = *(const float4*)(bp);
    float4 b1 = *(const float4*)(bp + 4);

    for (int k0 = 0; k0 < CDIM; k0 += 16) {
        // stage A transposed
        As[aq * 8 + 0][ar] = a0.x; As[aq * 8 + 1][ar] = a0.y;
        As[aq * 8 + 2][ar] = a0.z; As[aq * 8 + 3][ar] = a0.w;
        As[aq * 8 + 4][ar] = a1.x; As[aq * 8 + 5][ar] = a1.y;
        As[aq * 8 + 6][ar] = a1.z; As[aq * 8 + 7][ar] = a1.w;
        // stage B straight
        *(float4*)&Bs[bkr][bcq * 8]     = b0;
        *(float4*)&Bs[bkr][bcq * 8 + 4] = b1;
        __syncthreads();

        if (k0 + 16 < CDIM) {
            a0 = *(const float4*)(xpa + k0 + 16);
            a1 = *(const float4*)(xpa + k0 + 20);
            b0 = *(const float4*)(bp + (size_t)(k0 + 16) * CDIM);
            b1 = *(const float4*)(bp + (size_t)(k0 + 16) * CDIM + 4);
        }

        #pragma unroll
        for (int k = 0; k < 16; k++) {
            float4 av0 = *(const float4*)&As[k][ty * 8];        // broadcast
            float4 av1 = *(const float4*)&As[k][ty * 8 + 4];    // broadcast
            ulonglong2 q0 = *(const ulonglong2*)&Bs[k][tx * 4];
            ulonglong2 q1 = *(const ulonglong2*)&Bs[k][64 + tx * 4];
            unsigned long long bb0 = q0.x, bb1 = q0.y, bb2 = q1.x, bb3 = q1.y;
            float avv[8] = {av0.x, av0.y, av0.z, av0.w, av1.x, av1.y, av1.z, av1.w};
            #pragma unroll
            for (int i = 0; i < 8; i++) {
                unsigned long long ad;
                PACK2(ad, avv[i], avv[i]);
                FMA2(acc[i][0], ad, bb0);
                FMA2(acc[i][1], ad, bb1);
                FMA2(acc[i][2], ad, bb2);
                FMA2(acc[i][3], ad, bb3);
            }
        }
        __syncthreads();
    }

    // ---- epilogue: w = rs*acc + P - rs*mu*Q + bv2 ----
    float4 P0 = *(const float4*)(g_P + bn + tx * 4);
    float4 P1 = *(const float4*)(g_P + bn + 64 + tx * 4);
    float4 Q0 = *(const float4*)(g_Q + bn + tx * 4);
    float4 Q1 = *(const float4*)(g_Q + bn + 64 + tx * 4);
    float4 V0 = *(const float4*)(g_bv2 + bn + tx * 4);
    float4 V1 = *(const float4*)(g_bv2 + bn + 64 + tx * 4);
    #pragma unroll
    for (int i = 0; i < 8; i++) {
        const int rl = ty * 8 + i;
        const float rs = s_rs[rl];
        const float rm = rs * s_mu[rl];
        const int row = bm + rl;
        float2 p0 = unpack2(acc[i][0]);
        float2 p1 = unpack2(acc[i][1]);
        float2 p2 = unpack2(acc[i][2]);
        float2 p3 = unpack2(acc[i][3]);
        *(float4*)(g_w + (size_t)row * CDIM + bn + tx * 4) = make_float4(
            fmaf(rs, p0.x, P0.x - rm * Q0.x + V0.x),
            fmaf(rs, p0.y, P0.y - rm * Q0.y + V0.y),
            fmaf(rs, p1.x, P0.z - rm * Q0.z + V0.z),
            fmaf(rs, p1.y, P0.w - rm * Q0.w + V0.w));
        *(float4*)(g_w + (size_t)row * CDIM + bn + 64 + tx * 4) = make_float4(
            fmaf(rs, p2.x, P1.x - rm * Q1.x + V1.x),
            fmaf(rs, p2.y, P1.y - rm * Q1.y + V1.y),
            fmaf(rs, p3.x, P1.z - rm * Q1.z + V1.z),
            fmaf(rs, p3.y, P1.w - rm * Q1.w + V1.w));
    }
}

// ---------------- K3: main streaming pass over y + softmax + z-sum ----------------
__global__ void attn_kernel(const float* __restrict__ y, const float* __restrict__ z,
                            float* __restrict__ out) {
    const int row = blockIdx.x;    // b*M + m
    const int tid = threadIdx.x;   // 256 threads
    __shared__ __align__(16) float sw[CDIM];
    __shared__ float s8[8];
    __shared__ float sdot[NDIM];

    float wv = g_w[(size_t)row * CDIM + tid];
    sw[tid] = wv;
    float G = blockSum256(wv, s8);   // includes syncthreads -> sw visible

    const int n = tid >> 3, t8 = tid & 7;
    const float* yr = y + ((size_t)row * NDIM + n) * CDIM;
    float S1 = 0.f, S2 = 0.f, S3 = 0.f;
    #pragma unroll
    for (int j = 0; j < 8; j++) {
        const int col = j * 32 + t8 * 4;
        float4 yv = __ldcs((const float4*)(yr + col));
        float4 w4 = *(const float4*)(sw + col);
        S1 += yv.x + yv.y + yv.z + yv.w;
        S2 += yv.x * yv.x + yv.y * yv.y + yv.z * yv.z + yv.w * yv.w;
        S3 += yv.x * w4.x + yv.y * w4.y + yv.z * w4.z + yv.w * w4.w;
    }
    #pragma unroll
    for (int o = 4; o; o >>= 1) {
        S1 += __shfl_down_sync(0xffffffffu, S1, o);
        S2 += __shfl_down_sync(0xffffffffu, S2, o);
        S3 += __shfl_down_sync(0xffffffffu, S3, o);
    }
    if (t8 == 0) {
        float mu = S1 * (1.f / CDIM);
        float var = S2 * (1.f / CDIM) - mu * mu;
        float rs = rsqrtf(var + LN_EPS);
        sdot[n] = SCALE * (rs * (S3 - mu * G) + g_Bc[row]);
    }
    __syncthreads();
    if (tid < NDIM) {
        float v = sdot[tid];
        float m = v;
        #pragma unroll
        for (int o = 16; o; o >>= 1) m = fmaxf(m, __shfl_xor_sync(0xffffffffu, m, o));
        float e = expf(v - m);
        float zb = z[(size_t)row * NDIM + tid];
        float se = e, sez = e * zb;
        #pragma unroll
        for (int o = 16; o; o >>= 1) {
            se += __shfl_xor_sync(0xffffffffu, se, o);
            sez += __shfl_xor_sync(0xffffffffu, sez, o);
        }
        if (tid == 0) out[row] = sez / se;
    }
}

// ---------------- launch ----------------
extern "C" void kernel_launch(void* const* d_in, const int* in_sizes, int n_in,
                              void* d_out, int out_size) {
    const float* x  = (const float*)d_in[0];
    const float* y  = (const float*)d_in[1];
    const float* z  = (const float*)d_in[2];
    const float* qg = (const float*)d_in[3];
    const float* qb = (const float*)d_in[4];
    const float* Wq = (const float*)d_in[5];
    const float* bq = (const float*)d_in[6];
    const float* kg = (const float*)d_in[7];
    const float* kb = (const float*)d_in[8];
    const float* Wk = (const float*)d_in[9];
    const float* bk = (const float*)d_in[10];
    float* out = (float*)d_out;

    prepA_kernel<<<dim3(4, 4), 256>>>(Wq, Wk);
    prepB_kernel<<<CDIM + 2, 256>>>(Wq, Wk, bq, bk, kg, kb, qg, qb);
    gemm_kernel<<<dim3(2, ROWS / 128), 256>>>(x, qb);
    attn_kernel<<<ROWS, 256>>>(y, z, out);
}

// round 13
// speedup vs baseline: 1.9618x; 1.0751x over previous
#include <cuda_runtime.h>
#include <cuda_bf16.h>
#include <cstdint>

// Problem constants (fixed by setup_inputs)
#define BATCH 4
#define MDIM 4096
#define NDIM 32
#define CDIM 256
#define DDIM 128
#define ROWS (BATCH * MDIM)        // 16384
#define LN_EPS 1e-5f
#define SCALE 0.08838834764831845f // 1/sqrt(128)

// ---------------- scratch (device globals, no allocation) ----------------
__device__ __align__(16) float g_Mraw[CDIM * CDIM]; // Wq @ Wk^T
__device__ __align__(16) float g_M3[CDIM * CDIM];   // qg[k] * Mraw[k][c] * kg[c]
__device__ __align__(16) float g_P[CDIM];           // kg[c] * (qb @ Mraw)[c]
__device__ __align__(16) float g_Q[CDIM];           // kg[c] * (qg @ Mraw)[c]
__device__ __align__(16) float g_bv2[CDIM];         // kg[c] * (Wk[c,:]·bq)
__device__ __align__(16) float g_rowvec[CDIM];      // mb[c] + u[c]
__device__ __align__(16) float g_e[CDIM];           // qg ⊙ rowvec
__device__ float g_const[1];                        // bq·(Wk^T kb + bk)
__device__ __align__(16) float g_w[ROWS * CDIM];    // per-row weight vectors
__device__ float g_Bc[ROWS];                        // per-row scalar bias

// ---------------- helpers ----------------
__device__ __forceinline__ float blockSum256(float v, float* s8) {
    #pragma unroll
    for (int o = 16; o; o >>= 1) v += __shfl_xor_sync(0xffffffffu, v, o);
    __syncthreads();
    if ((threadIdx.x & 31) == 0) s8[threadIdx.x >> 5] = v;
    __syncthreads();
    float tot = 0.f;
    #pragma unroll
    for (int i = 0; i < 8; i++) tot += s8[i];
    return tot;
}

#define FMA2(d, a, b) \
    asm("fma.rn.f32x2 %0, %1, %2, %0;" : "+l"(d) : "l"(a), "l"(b))
#define PACK2(out, lo, hi) \
    asm("mov.b64 %0, {%1, %2};" : "=l"(out) : "r"(__float_as_uint(lo)), "r"(__float_as_uint(hi)))

__device__ __forceinline__ float2 unpack2(unsigned long long v) {
    unsigned int lo, hi;
    asm("mov.b64 {%0, %1}, %2;" : "=r"(lo), "=r"(hi) : "l"(v));
    return make_float2(__uint_as_float(lo), __uint_as_float(hi));
}

// ---------------- K1a: Mraw = Wq(256x128) @ Wk^T(128x256), tiled ----------------
__global__ void prepA_kernel(const float* __restrict__ Wq, const float* __restrict__ Wk) {
    __shared__ float As[32][68];
    __shared__ float Bs[32][68];
    const int bm = blockIdx.y * 64;
    const int bn = blockIdx.x * 64;
    const int tid = threadIdx.x;
    const int tx = tid & 15, ty = tid >> 4;
    const int r = tid >> 2, dq = tid & 3;

    float acc[4][4];
    #pragma unroll
    for (int i = 0; i < 4; i++)
        #pragma unroll
        for (int j = 0; j < 4; j++) acc[i][j] = 0.f;

    for (int k0 = 0; k0 < DDIM; k0 += 32) {
        float4 a0 = *(const float4*)(Wq + (size_t)(bm + r) * DDIM + k0 + dq * 8);
        float4 a1 = *(const float4*)(Wq + (size_t)(bm + r) * DDIM + k0 + dq * 8 + 4);
        float4 b0 = *(const float4*)(Wk + (size_t)(bn + r) * DDIM + k0 + dq * 8);
        float4 b1 = *(const float4*)(Wk + (size_t)(bn + r) * DDIM + k0 + dq * 8 + 4);
        As[dq * 8 + 0][r] = a0.x; As[dq * 8 + 1][r] = a0.y;
        As[dq * 8 + 2][r] = a0.z; As[dq * 8 + 3][r] = a0.w;
        As[dq * 8 + 4][r] = a1.x; As[dq * 8 + 5][r] = a1.y;
        As[dq * 8 + 6][r] = a1.z; As[dq * 8 + 7][r] = a1.w;
        Bs[dq * 8 + 0][r] = b0.x; Bs[dq * 8 + 1][r] = b0.y;
        Bs[dq * 8 + 2][r] = b0.z; Bs[dq * 8 + 3][r] = b0.w;
        Bs[dq * 8 + 4][r] = b1.x; Bs[dq * 8 + 5][r] = b1.y;
        Bs[dq * 8 + 6][r] = b1.z; Bs[dq * 8 + 7][r] = b1.w;
        __syncthreads();
        #pragma unroll
        for (int k = 0; k < 32; k++) {
            float4 a = *(const float4*)&As[k][ty * 4];
            float4 b = *(const float4*)&Bs[k][tx * 4];
            float ai[4] = {a.x, a.y, a.z, a.w};
            float bj[4] = {b.x, b.y, b.z, b.w};
            #pragma unroll
            for (int i = 0; i < 4; i++)
                #pragma unroll
                for (int j = 0; j < 4; j++) acc[i][j] += ai[i] * bj[j];
        }
        __syncthreads();
    }
    #pragma unroll
    for (int i = 0; i < 4; i++)
        *(float4*)(g_Mraw + (size_t)(bm + ty * 4 + i) * CDIM + bn + tx * 4) =
            make_float4(acc[i][0], acc[i][1], acc[i][2], acc[i][3]);
}

// ---------------- K1b: derived vectors; blocks 0..255 per-row, 256: P/Q, 257: const ----------------
__global__ void prepB_kernel(const float* __restrict__ Wq, const float* __restrict__ Wk,
                             const float* __restrict__ bq, const float* __restrict__ bk,
                             const float* __restrict__ kg, const float* __restrict__ kb,
                             const float* __restrict__ qg, const float* __restrict__ qb) {
    const int c = blockIdx.x;
    const int t = threadIdx.x;
    __shared__ float s8[8];
    __shared__ float sA[CDIM], sB[CDIM];

    if (c < CDIM) {
        float mraw = g_Mraw[(size_t)c * CDIM + t];
        g_M3[(size_t)c * CDIM + t] = mraw * kg[t] * qg[c];
        float mb = blockSum256(mraw * kb[t], s8);
        float u  = blockSum256(t < DDIM ? Wq[(size_t)c * DDIM + t] * bk[t] : 0.f, s8);
        float bv = blockSum256(t < DDIM ? Wk[(size_t)c * DDIM + t] * bq[t] : 0.f, s8);
        if (t == 0) {
            float rv = mb + u;
            g_rowvec[c] = rv;
            g_e[c] = qg[c] * rv;
            g_bv2[c] = bv * kg[c];
        }
    } else if (c == CDIM) {
        sA[t] = qb[t];
        sB[t] = qg[t];
        __syncthreads();
        float accP = 0.f, accQ = 0.f;
        for (int k = 0; k < CDIM; k++) {
            float m = g_Mraw[(size_t)k * CDIM + t];   // coalesced over t
            accP += sA[k] * m;
            accQ += sB[k] * m;
        }
        float kgt = kg[t];
        g_P[t] = kgt * accP;
        g_Q[t] = kgt * accQ;
    } else {
        float acc = 0.f;
        if (t < DDIM) {
            for (int c2 = 0; c2 < CDIM; c2++) acc += Wk[(size_t)c2 * DDIM + t] * kb[c2];
            acc = (acc + bk[t]) * bq[t];
        }
        float tot = blockSum256(acc, s8);
        if (t == 0) g_const[0] = tot;
    }
}

// ---------------- K2: GEMM acc = x @ M3 ; 128x128 tile, 8x8/thread, BK=16, double-buffered ----------------
__global__ void __launch_bounds__(256, 2)
gemm_kernel(const float* __restrict__ x, const float* __restrict__ qb) {
    __shared__ __align__(16) float As[2][16][132];   // [buf][k][m]
    __shared__ __align__(16) float Bs[2][16][132];   // [buf][k][n]
    __shared__ float s_mu[128], s_rs[128];
    __shared__ __align__(16) float s_e[CDIM];
    __shared__ float s8[8];

    const int bm = blockIdx.y * 128;
    const int bn = blockIdx.x * 128;
    const int tid = threadIdx.x;

    // ---- phase 0: e into smem; E, F block scalars ----
    float ev = g_e[tid];
    s_e[tid] = ev;
    float E = blockSum256(ev, s8);
    float F = blockSum256(qb[tid] * g_rowvec[tid], s8);

    // ---- phase 1: per-row stats, 2 threads per row (also warms x tile in L1) ----
    {
        const int ar = tid >> 1, half = tid & 1;
        const float* xr = x + (size_t)(bm + ar) * CDIM + half * 4;
        float s1 = 0.f, s2 = 0.f, s3 = 0.f;
        #pragma unroll
        for (int j = 0; j < 32; j++) {
            float4 v = *(const float4*)(xr + j * 8);
            const float* ep = s_e + half * 4 + j * 8;
            s1 += v.x + v.y + v.z + v.w;
            s2 += v.x * v.x + v.y * v.y + v.z * v.z + v.w * v.w;
            s3 += v.x * ep[0] + v.y * ep[1] + v.z * ep[2] + v.w * ep[3];
        }
        s1 += __shfl_xor_sync(0xffffffffu, s1, 1);
        s2 += __shfl_xor_sync(0xffffffffu, s2, 1);
        s3 += __shfl_xor_sync(0xffffffffu, s3, 1);
        if (half == 0) {
            float mu = s1 * (1.f / CDIM);
            float var = s2 * (1.f / CDIM) - mu * mu;
            float rs = rsqrtf(var + LN_EPS);
            s_mu[ar] = mu;
            s_rs[ar] = rs;
            if (blockIdx.x == 0)
                g_Bc[bm + ar] = rs * (s3 - mu * E) + F + g_const[0];
        }
    }
    __syncthreads();

    // ---- main loop: raw x @ M3, BK=16, double-buffered smem, 8x8 per thread ----
    const int ar = tid >> 1, aq = tid & 1;          // A staging: row, k-octet
    const int bkr = tid >> 4, bcq = tid & 15;       // B staging: k-row, col-octet
    const int tx = tid & 15, ty = tid >> 4;         // compute mapping

    const float* xpa = x + (size_t)(bm + ar) * CDIM + aq * 8;
    const float* bp  = g_M3 + (size_t)bkr * CDIM + bn + bcq * 8;

    unsigned long long acc[8][4];
    #pragma unroll
    for (int i = 0; i < 8; i++)
        #pragma unroll
        for (int j = 0; j < 4; j++) acc[i][j] = 0ull;

    // prologue: stage slab 0 into buffer 0
    {
        float4 a0 = *(const float4*)(xpa);
        float4 a1 = *(const float4*)(xpa + 4);
        float4 b0 = *(const float4*)(bp);
        float4 b1 = *(const float4*)(bp + 4);
        As[0][aq * 8 + 0][ar] = a0.x; As[0][aq * 8 + 1][ar] = a0.y;
        As[0][aq * 8 + 2][ar] = a0.z; As[0][aq * 8 + 3][ar] = a0.w;
        As[0][aq * 8 + 4][ar] = a1.x; As[0][aq * 8 + 5][ar] = a1.y;
        As[0][aq * 8 + 6][ar] = a1.z; As[0][aq * 8 + 7][ar] = a1.w;
        *(float4*)&Bs[0][bkr][bcq * 8]     = b0;
        *(float4*)&Bs[0][bkr][bcq * 8 + 4] = b1;
    }
    __syncthreads();

    #pragma unroll 1
    for (int k0 = 0; k0 < CDIM; k0 += 16) {
        const int b = (k0 >> 4) & 1;
        const bool has_next = (k0 + 16 < CDIM);

        // issue next slab's global loads early (latency hides under compute)
        float4 a0, a1, b0, b1;
        if (has_next) {
            a0 = *(const float4*)(xpa + k0 + 16);
            a1 = *(const float4*)(xpa + k0 + 20);
            b0 = *(const float4*)(bp + (size_t)(k0 + 16) * CDIM);
            b1 = *(const float4*)(bp + (size_t)(k0 + 16) * CDIM + 4);
        }

        // compute from buffer b
        #pragma unroll
        for (int k = 0; k < 16; k++) {
            float4 av0 = *(const float4*)&As[b][k][ty * 8];        // broadcast
            float4 av1 = *(const float4*)&As[b][k][ty * 8 + 4];    // broadcast
            ulonglong2 q0 = *(const ulonglong2*)&Bs[b][k][tx * 4];
            ulonglong2 q1 = *(const ulonglong2*)&Bs[b][k][64 + tx * 4];
            unsigned long long bb0 = q0.x, bb1 = q0.y, bb2 = q1.x, bb3 = q1.y;
            float avv[8] = {av0.x, av0.y, av0.z, av0.w, av1.x, av1.y, av1.z, av1.w};
            #pragma unroll
            for (int i = 0; i < 8; i++) {
                unsigned long long ad;
                PACK2(ad, avv[i], avv[i]);
                FMA2(acc[i][0], ad, bb0);
                FMA2(acc[i][1], ad, bb1);
                FMA2(acc[i][2], ad, bb2);
                FMA2(acc[i][3], ad, bb3);
            }
        }

        // stage next slab into the other buffer
        if (has_next) {
            const int nb = b ^ 1;
            As[nb][aq * 8 + 0][ar] = a0.x; As[nb][aq * 8 + 1][ar] = a0.y;
            As[nb][aq * 8 + 2][ar] = a0.z; As[nb][aq * 8 + 3][ar] = a0.w;
            As[nb][aq * 8 + 4][ar] = a1.x; As[nb][aq * 8 + 5][ar] = a1.y;
            As[nb][aq * 8 + 6][ar] = a1.z; As[nb][aq * 8 + 7][ar] = a1.w;
            *(float4*)&Bs[nb][bkr][bcq * 8]     = b0;
            *(float4*)&Bs[nb][bkr][bcq * 8 + 4] = b1;
            __syncthreads();
        }
    }

    // ---- epilogue: w = rs*acc + P - rs*mu*Q + bv2 ----
    float4 P0 = *(const float4*)(g_P + bn + tx * 4);
    float4 P1 = *(const float4*)(g_P + bn + 64 + tx * 4);
    float4 Q0 = *(const float4*)(g_Q + bn + tx * 4);
    float4 Q1 = *(const float4*)(g_Q + bn + 64 + tx * 4);
    float4 V0 = *(const float4*)(g_bv2 + bn + tx * 4);
    float4 V1 = *(const float4*)(g_bv2 + bn + 64 + tx * 4);
    #pragma unroll
    for (int i = 0; i < 8; i++) {
        const int rl = ty * 8 + i;
        const float rs = s_rs[rl];
        const float rm = rs * s_mu[rl];
        const int row = bm + rl;
        float2 p0 = unpack2(acc[i][0]);
        float2 p1 = unpack2(acc[i][1]);
        float2 p2 = unpack2(acc[i][2]);
        float2 p3 = unpack2(acc[i][3]);
        *(float4*)(g_w + (size_t)row * CDIM + bn + tx * 4) = make_float4(
            fmaf(rs, p0.x, P0.x - rm * Q0.x + V0.x),
            fmaf(rs, p0.y, P0.y - rm * Q0.y + V0.y),
            fmaf(rs, p1.x, P0.z - rm * Q0.z + V0.z),
            fmaf(rs, p1.y, P0.w - rm * Q0.w + V0.w));
        *(float4*)(g_w + (size_t)row * CDIM + bn + 64 + tx * 4) = make_float4(
            fmaf(rs, p2.x, P1.x - rm * Q1.x + V1.x),
            fmaf(rs, p2.y, P1.y - rm * Q1.y + V1.y),
            fmaf(rs, p3.x, P1.z - rm * Q1.z + V1.z),
            fmaf(rs, p3.y, P1.w - rm * Q1.w + V1.w));
    }
}

// ---------------- K3: main streaming pass over y + softmax + z-sum ----------------
__global__ void attn_kernel(const float* __restrict__ y, const float* __restrict__ z,
                            float* __restrict__ out) {
    const int row = blockIdx.x;    // b*M + m
    const int tid = threadIdx.x;   // 256 threads
    __shared__ __align__(16) float sw[CDIM];
    __shared__ float s8[8];
    __shared__ float sdot[NDIM];

    // issue all y loads first — latency hides under the w reduction below
    const int n = tid >> 3, t8 = tid & 7;
    const float* yr = y + ((size_t)row * NDIM + n) * CDIM;
    float4 yv[8];
    #pragma unroll
    for (int j = 0; j < 8; j++)
        yv[j] = __ldcs((const float4*)(yr + j * 32 + t8 * 4));

    float wv = g_w[(size_t)row * CDIM + tid];
    sw[tid] = wv;
    float G = blockSum256(wv, s8);   // includes syncthreads -> sw visible

    float S1 = 0.f, S2 = 0.f, S3 = 0.f;
    #pragma unroll
    for (int j = 0; j < 8; j++) {
        float4 w4 = *(const float4*)(sw + j * 32 + t8 * 4);
        S1 += yv[j].x + yv[j].y + yv[j].z + yv[j].w;
        S2 += yv[j].x * yv[j].x + yv[j].y * yv[j].y + yv[j].z * yv[j].z + yv[j].w * yv[j].w;
        S3 += yv[j].x * w4.x + yv[j].y * w4.y + yv[j].z * w4.z + yv[j].w * w4.w;
    }
    #pragma unroll
    for (int o = 4; o; o >>= 1) {
        S1 += __shfl_down_sync(0xffffffffu, S1, o);
        S2 += __shfl_down_sync(0xffffffffu, S2, o);
        S3 += __shfl_down_sync(0xffffffffu, S3, o);
    }
    if (t8 == 0) {
        float mu = S1 * (1.f / CDIM);
        float var = S2 * (1.f / CDIM) - mu * mu;
        float rs = rsqrtf(var + LN_EPS);
        sdot[n] = SCALE * (rs * (S3 - mu * G) + g_Bc[row]);
    }
    __syncthreads();
    if (tid < NDIM) {
        float v = sdot[tid];
        float m = v;
        #pragma unroll
        for (int o = 16; o; o >>= 1) m = fmaxf(m, __shfl_xor_sync(0xffffffffu, m, o));
        float e = expf(v - m);
        float zb = z[(size_t)row * NDIM + tid];
        float se = e, sez = e * zb;
        #pragma unroll
        for (int o = 16; o; o >>= 1) {
            se += __shfl_xor_sync(0xffffffffu, se, o);
            sez += __shfl_xor_sync(0xffffffffu, sez, o);
        }
        if (tid == 0) out[row] = sez / se;
    }
}

// ---------------- launch ----------------
extern "C" void kernel_launch(void* const* d_in, const int* in_sizes, int n_in,
                              void* d_out, int out_size) {
    const float* x  = (const float*)d_in[0];
    const float* y  = (const float*)d_in[1];
    const float* z  = (const float*)d_in[2];
    const float* qg = (const float*)d_in[3];
    const float* qb = (const float*)d_in[4];
    const float* Wq = (const float*)d_in[5];
    const float* bq = (const float*)d_in[6];
    const float* kg = (const float*)d_in[7];
    const float* kb = (const float*)d_in[8];
    const float* Wk = (const float*)d_in[9];
    const float* bk = (const float*)d_in[10];
    float* out = (float*)d_out;

    prepA_kernel<<<dim3(4, 4), 256>>>(Wq, Wk);
    prepB_kernel<<<CDIM + 2, 256>>>(Wq, Wk, bq, bk, kg, kb, qg, qb);
    gemm_kernel<<<dim3(2, ROWS / 128), 256>>>(x, qb);
    attn_kernel<<<ROWS, 256>>>(y, z, out);
}